// round 11
// baseline (speedup 1.0000x reference)
#include <cuda_runtime.h>
#include <cstdint>

#define HID   100
#define GROWS 400
#define TENC  4096
#define TDEC  4096
#define NCLS  6
#define NTH   256          // 8 warps: tid 0-199 matvec (4 gate rows of unit j, half-K), warp 7 logits
#define LOG2E 1.4426950408889634f

typedef unsigned long long ull;

// precomputed input contributions, packed [t][j][4] = (i,f,g,o) of hidden unit j
__device__ float g_gge[TENC * GROWS];   // encoder
__device__ float g_ggd[TDEC * GROWS];   // decoder

// ---- packed f32x2 helpers ----
__device__ __forceinline__ ull fma2(ull a, ull b, ull c) {
    ull d;
    asm("fma.rn.f32x2 %0, %1, %2, %3;" : "=l"(d) : "l"(a), "l"(b), "l"(c));
    return d;
}
__device__ __forceinline__ float ex2f(float x) {
    float y; asm("ex2.approx.f32 %0, %1;" : "=f"(y) : "f"(x)); return y;
}
__device__ __forceinline__ float rcpf(float x) {
    float y; asm("rcp.approx.f32 %0, %1;" : "=f"(y) : "f"(x)); return y;
}
__device__ __forceinline__ float sigf(float x) {
    return rcpf(1.0f + ex2f(-LOG2E * x));
}
__device__ __forceinline__ float tanhf_fast(float x) {
    return 1.0f - 2.0f * rcpf(1.0f + ex2f((2.0f * LOG2E) * x));
}
__device__ __forceinline__ float hsum2(ull s) {
    float lo, hi;
    asm("mov.b64 {%0,%1},%2;" : "=f"(lo), "=f"(hi) : "l"(s));
    return lo + hi;
}

// ---------------- prep kernel: gx precompute (fully parallel) ----------------
__global__ void gx_prep_kernel(const float* __restrict__ x,     // [TENC,3]
                               const int*   __restrict__ y,     // [TDEC]
                               const float* __restrict__ eWih,  // [400,3]
                               const float* __restrict__ ebih,
                               const float* __restrict__ ebhh,
                               const float* __restrict__ dWih,  // [400,1]
                               const float* __restrict__ dbih,
                               const float* __restrict__ dbhh)
{
    int idx = blockIdx.x * blockDim.x + threadIdx.x;
    if (idx >= TENC * GROWS) return;
    int t = idx / GROWS;
    int r = idx - t * GROWS;
    int j = r % 100, gate = r / 100;          // gate: 0=i,1=f,2=g,3=o
    int dst = t * GROWS + j * 4 + gate;
    g_gge[dst] = ebih[r] + ebhh[r]
               + x[3*t+0] * eWih[3*r+0]
               + x[3*t+1] * eWih[3*r+1]
               + x[3*t+2] * eWih[3*r+2];
    g_ggd[dst] = dbih[r] + dbhh[r] + (float)y[t] * dWih[r];
}

// weight slice: 4 gate rows of unit j, cols [half*52, half*52+52) (pad 100-103 = 0)
__device__ __forceinline__ void load_w(ull (&w)[104], const float* __restrict__ Whh,
                                       int j, int half) {
#pragma unroll
    for (int g = 0; g < 4; ++g) {
        const int row = j + g * 100;
        const ull* wr = (const ull*)(Whh + row * HID + half * 52);
        if (half == 0) {
#pragma unroll
            for (int k = 0; k < 26; ++k) w[g * 26 + k] = wr[k];
        } else {
#pragma unroll
            for (int k = 0; k < 24; ++k) w[g * 26 + k] = wr[k];
            w[g * 26 + 24] = 0ull;
            w[g * 26 + 25] = 0ull;
        }
    }
}

// Four 52-col partial dots (one per gate row), 3-deep pipelined LDS.128.
__device__ __forceinline__ void dotquad(const ull (&w)[104], unsigned hb,
                                        float& s0, float& s1, float& s2, float& s3)
{
    ull bx[3], by[3];
#pragma unroll
    for (int m = 0; m < 3; ++m)
        asm volatile("ld.shared.v2.b64 {%0,%1},[%2];"
                     : "=l"(bx[m]), "=l"(by[m]) : "r"(hb + 16u * m));
    ull a0 = 0ull, a1 = 0ull, a2 = 0ull, a3 = 0ull;
#pragma unroll
    for (int k = 0; k < 13; ++k) {
        const int sl = k % 3;
        const ull hx = bx[sl], hy = by[sl];
        if (k + 3 < 13)
            asm volatile("ld.shared.v2.b64 {%0,%1},[%2];"
                         : "=l"(bx[sl]), "=l"(by[sl]) : "r"(hb + 16u * (k + 3)));
        a0 = fma2(w[      2*k], hx, a0); a0 = fma2(w[      2*k+1], hy, a0);
        a1 = fma2(w[ 26 + 2*k], hx, a1); a1 = fma2(w[ 26 + 2*k+1], hy, a1);
        a2 = fma2(w[ 52 + 2*k], hx, a2); a2 = fma2(w[ 52 + 2*k+1], hy, a2);
        a3 = fma2(w[ 78 + 2*k], hx, a3); a3 = fma2(w[ 78 + 2*k+1], hy, a3);
    }
    s0 = hsum2(a0); s1 = hsum2(a1); s2 = hsum2(a2); s3 = hsum2(a3);
}

// One LSTM step for matvec threads (tid<200). Branchless clamped gx prefetch.
__device__ __forceinline__ void lstm_body(
    const float* __restrict__ gg, int s, int T,
    const ull (&w)[104],
    unsigned hbRead, float* __restrict__ hWrite,
    float4& gx, float& c,
    int j, int half, unsigned mvmask)
{
    int sn = s + 1; if (sn > T - 1) sn = T - 1;
    const float4 nx = __ldg(((const float4*)(gg + sn * GROWS)) + j);

    float s0, s1, s2, s3;
    dotquad(w, hbRead + (unsigned)(half * 208), s0, s1, s2, s3);

    // combine halves (pair lanes 2j / 2j+1), then add gx once per lane
    const float r0 = s0 + __shfl_xor_sync(mvmask, s0, 1) + gx.x;
    const float r1 = s1 + __shfl_xor_sync(mvmask, s1, 1) + gx.y;
    const float r2 = s2 + __shfl_xor_sync(mvmask, s2, 1) + gx.z;
    const float r3 = s3 + __shfl_xor_sync(mvmask, s3, 1) + gx.w;

    const float iv = sigf(r0);
    const float fv = sigf(r1);
    const float gv = tanhf_fast(r2);
    const float ov = sigf(r3);
    c = fmaf(fv, c, iv * gv);
    const float h = ov * tanhf_fast(c);
    if (half == 0) hWrite[j] = h;
    gx = nx;
}

// Logits of one decoder step (warp 7 only).
__device__ __forceinline__ void logits_body(
    const float* __restrict__ hRead,
    const float* __restrict__ slw, const float* __restrict__ slb,
    float* __restrict__ out, int orow, int cls, int piece)
{
    float acc = 0.0f;
    const float* lp = slw + cls * HID + piece * 25;   // cls 6,7 hit zero pad
    const float* hq = hRead + piece * 25;
#pragma unroll
    for (int k = 0; k < 25; ++k)
        acc = fmaf(lp[k], hq[k], acc);
    acc += __shfl_xor_sync(0xffffffffu, acc, 8);
    acc += __shfl_xor_sync(0xffffffffu, acc, 16);
    if (piece == 0 && cls < NCLS)
        out[orow * NCLS + cls] = acc + slb[cls];
}

// ---------------- persistent recurrence kernel ----------------
__global__ void __launch_bounds__(NTH, 1)
lstm_encdec_kernel(const float* __restrict__ eWhh,   // [400,100]
                   const float* __restrict__ dWhh,   // [400,100]
                   const float* __restrict__ linW,   // [6,100]
                   const float* __restrict__ linb,   // [6]
                   float* __restrict__ out)          // [TDEC,6]
{
    __shared__ __align__(1024) float hbuf[2][128];   // h padded to 104+ (pad = 0)
    __shared__ float slw[8 * HID];                   // lin_W padded to 8 rows
    __shared__ float slb[NCLS];

    const int tid = threadIdx.x;

    // ---- init (zero full padded rows: odd halves read cols 100-103) ----
    if (tid < 128) { hbuf[0][tid] = 0.0f; hbuf[1][tid] = 0.0f; }
    if (tid < NCLS) { out[(TDEC - 1) * NCLS + tid] = 0.0f; slb[tid] = linb[tid]; }
    for (int i = tid; i < 8 * HID; i += NTH)
        slw[i] = (i < NCLS * HID) ? linW[i] : 0.0f;
    float c = 0.0f;                                  // both lanes of pair keep c[j]

    const bool mv   = (tid < 200);
    const bool lwrp = ((tid >> 5) == 7);
    const int  j    = tid >> 1;
    const int  half = tid & 1;
    const int lane  = tid & 31;
    const int cls   = lane & 7;
    const int piece = lane >> 3;
    const unsigned mvmask = (tid >= 192) ? 0xFFu : 0xFFFFFFFFu;

    // ---- encoder weights (208 regs) ----
    ull w[104];
    if (mv) load_w(w, eWhh, j, half);
    __syncthreads();

    const unsigned hb0 = (unsigned)__cvta_generic_to_shared(&hbuf[0][0]);
    const unsigned hb1 = hb0 + 512u;
    float* const h0 = &hbuf[0][0];
    float* const h1 = &hbuf[1][0];

    // gx for step 0
    float4 gx = make_float4(0.f, 0.f, 0.f, 0.f);
    if (mv) gx = __ldg(((const float4*)g_gge) + j);

    // ================= encoder: 4096 steps, ping-pong =================
#pragma unroll 1
    for (int s = 0; s < TENC; s += 2) {
        if (mv) lstm_body(g_gge, s,     TENC, w, hb0, h1, gx, c, j, half, mvmask);
        __syncthreads();
        if (mv) lstm_body(g_gge, s + 1, TENC, w, hb1, h0, gx, c, j, half, mvmask);
        __syncthreads();
    }
    // h_enc in hbuf[0]

    // ---- decoder weights (registers only) ----
    if (mv) {
        load_w(w, dWhh, j, half);
        gx = __ldg(((const float4*)g_ggd) + j);
    }

    // ================= decoder =================
#pragma unroll 1
    for (int s = 0; s < TDEC - 2; s += 2) {
        if (mv) {
            lstm_body(g_ggd, s, TDEC, w, hb0, h1, gx, c, j, half, mvmask);
        } else if (lwrp && s >= 1) {
            logits_body(h0, slw, slb, out, s - 1, cls, piece);
        }
        __syncthreads();
        if (mv) {
            lstm_body(g_ggd, s + 1, TDEC, w, hb1, h0, gx, c, j, half, mvmask);
        } else if (lwrp) {
            logits_body(h1, slw, slb, out, s, cls, piece);
        }
        __syncthreads();
    }
    // step 4094: reads hbuf[0] -> writes hbuf[1]; logits of 4093 from hbuf[0]
    if (mv) {
        lstm_body(g_ggd, TDEC - 2, TDEC, w, hb0, h1, gx, c, j, half, mvmask);
    } else if (lwrp) {
        logits_body(h0, slw, slb, out, TDEC - 3, cls, piece);
    }
    __syncthreads();
    // logits of step 4094 from hbuf[1] (row 4095 stays zero)
    if (lwrp) logits_body(h1, slw, slb, out, TDEC - 2, cls, piece);
}

extern "C" void kernel_launch(void* const* d_in, const int* in_sizes, int n_in,
                              void* d_out, int out_size) {
    const float* x     = (const float*)d_in[0];
    const int*   y     = (const int*)  d_in[1];
    const float* eWih  = (const float*)d_in[2];
    const float* eWhh  = (const float*)d_in[3];
    const float* ebih  = (const float*)d_in[4];
    const float* ebhh  = (const float*)d_in[5];
    const float* dWih  = (const float*)d_in[6];
    const float* dWhh  = (const float*)d_in[7];
    const float* dbih  = (const float*)d_in[8];
    const float* dbhh  = (const float*)d_in[9];
    const float* linW  = (const float*)d_in[10];
    const float* linb  = (const float*)d_in[11];
    float* out = (float*)d_out;

    const int n = TENC * GROWS;
    gx_prep_kernel<<<(n + 255) / 256, 256>>>(x, y, eWih, ebih, ebhh,
                                             dWih, dbih, dbhh);
    lstm_encdec_kernel<<<1, NTH>>>(eWhh, dWhh, linW, linb, out);
}